// round 1
// baseline (speedup 1.0000x reference)
#include <cuda_runtime.h>
#include <cuda_bf16.h>
#include <cstdint>

// Problem constants
#define NPTS   32768
#define DK     512
#define NC0    1024          // main codes
#define NC1    512           // sub codebook 1
#define NC2    256           // sub codebook 2
#define NCODES 1792          // total
#define CB1_OFF 1024
#define CB2_OFF 1536

// d_out layout (flattened outputs in return order, fp32):
// main_out [1,N,DK] | sub_out [1,N,DK] | total_loss [1] | ms_k_i [16,DK] | unique [1]
#define MAIN_OFF 0
#define SUB_OFF  (NPTS*DK)              // 16777216
#define LOSS_OFF (2*NPTS*DK)            // 33554432
#define MS_OFF   (LOSS_OFF + 1)         // 33554433
#define MS_N     (16*DK)                // 8192
#define UNIQ_OFF (MS_OFF + MS_N)        // 33562625

// Scratch (device globals; no allocation allowed)
__device__ float              g_cb[NCODES * DK];     // [c ; W1@c+b1 ; W2@c+b2]
__device__ float              g_halfnorm[NCODES];
__device__ unsigned long long g_amin[3 * NPTS];      // packed (orderable_score<<32 | local_idx)
__device__ float              g_loss[2];
__device__ int                g_used[NC0];

__device__ __forceinline__ unsigned int f2ord(float f) {
    unsigned int u = __float_as_uint(f);
    return (u & 0x80000000u) ? ~u : (u | 0x80000000u);
}

// ---------------------------------------------------------------------------
// init: reset argmin slots, used flags, loss accumulators; zero ms_k_i in out
// ---------------------------------------------------------------------------
__global__ void k_init(float* __restrict__ out) {
    int i = blockIdx.x * blockDim.x + threadIdx.x;
    if (i < 3 * NPTS) g_amin[i] = ~0ULL;
    if (i < MS_N)     out[MS_OFF + i] = 0.0f;
    if (i < NC0)      g_used[i] = 0;
    if (i < 2)        g_loss[i] = 0.0f;
}

// ---------------------------------------------------------------------------
// copy main codebook into g_cb[0 : NC0*DK)
// ---------------------------------------------------------------------------
__global__ void k_copy_c(const float* __restrict__ c) {
    int i = blockIdx.x * blockDim.x + threadIdx.x;   // float4 index
    if (i < NC0 * DK / 4)
        reinterpret_cast<float4*>(g_cb)[i] = reinterpret_cast<const float4*>(c)[i];
}

// ---------------------------------------------------------------------------
// sub codebooks: g_cb[1024+i] = W_row(i) @ c + b(i)   for i in [0,768)
// block: 8 output rows x 256 d-columns, K=1024 in chunks of 128
// ---------------------------------------------------------------------------
__global__ __launch_bounds__(256) void k_subc(
    const float* __restrict__ c,
    const float* __restrict__ W1, const float* __restrict__ b1,
    const float* __restrict__ W2, const float* __restrict__ b2)
{
    const int i0 = blockIdx.x * 8;                       // output row base (0..760)
    const int d  = blockIdx.y * 256 + threadIdx.x;       // 0..511
    __shared__ float Ws[8][128];

    float acc[8];
#pragma unroll
    for (int r = 0; r < 8; r++) acc[r] = 0.0f;

    for (int j0 = 0; j0 < NC0; j0 += 128) {
#pragma unroll
        for (int l = 0; l < 4; l++) {
            int p  = threadIdx.x + l * 256;
            int r  = p >> 7;
            int jj = p & 127;
            int gi = i0 + r;
            const float* Wrow = (gi < NC1) ? &W1[(size_t)gi * NC0]
                                           : &W2[(size_t)(gi - NC1) * NC0];
            Ws[r][jj] = Wrow[j0 + jj];
        }
        __syncthreads();
        for (int jj = 0; jj < 128; jj++) {
            float cv = c[(size_t)(j0 + jj) * DK + d];
#pragma unroll
            for (int r = 0; r < 8; r++) acc[r] += Ws[r][jj] * cv;
        }
        __syncthreads();
    }
#pragma unroll
    for (int r = 0; r < 8; r++) {
        int gi = i0 + r;
        float bias = (gi < NC1) ? b1[gi] : b2[gi - NC1];
        g_cb[(size_t)(CB1_OFF + gi) * DK + d] = acc[r] + bias;
    }
}

// ---------------------------------------------------------------------------
// half-norms of all 1792 codes (one warp per code)
// ---------------------------------------------------------------------------
__global__ void k_norm() {
    int warp = (blockIdx.x * blockDim.x + threadIdx.x) >> 5;
    int lane = threadIdx.x & 31;
    if (warp >= NCODES) return;
    float s = 0.0f;
    for (int dd = lane; dd < DK; dd += 32) {
        float v = g_cb[(size_t)warp * DK + dd];
        s += v * v;
    }
#pragma unroll
    for (int off = 16; off >= 1; off >>= 1)
        s += __shfl_xor_sync(0xffffffffu, s, off);
    if (lane == 0) g_halfnorm[warp] = 0.5f * s;
}

// ---------------------------------------------------------------------------
// main fused GEMM + argmin.
// score[n,m] = 0.5*||cb_m||^2 - x_n . cb_m   (same argmin as squared distance)
// Block tile: 128 rows x 64 codes, K-chunk 16. 256 threads, 8x4 per thread.
// ---------------------------------------------------------------------------
__global__ __launch_bounds__(256) void k_score(const float* __restrict__ x) {
    const int tid  = threadIdx.x;
    const int tx   = tid & 15;              // code sub-tile
    const int ty   = tid >> 4;              // row sub-tile
    const int row0 = blockIdx.x * 128;
    const int n0   = blockIdx.y * 64;

    __shared__ float Xs[16][128];
    __shared__ float Cs[16][64];

    float acc[8][4];
#pragma unroll
    for (int i = 0; i < 8; i++)
#pragma unroll
        for (int j = 0; j < 4; j++) acc[i][j] = 0.0f;

    for (int kc = 0; kc < DK; kc += 16) {
        // stage X tile (128x16) transposed
#pragma unroll
        for (int l = 0; l < 2; l++) {
            int p  = tid + l * 256;          // 0..511
            int r  = p >> 2;                 // 0..127
            int k4 = (p & 3) << 2;           // 0,4,8,12
            float4 v = *reinterpret_cast<const float4*>(
                &x[(size_t)(row0 + r) * DK + kc + k4]);
            Xs[k4 + 0][r] = v.x; Xs[k4 + 1][r] = v.y;
            Xs[k4 + 2][r] = v.z; Xs[k4 + 3][r] = v.w;
        }
        // stage CB tile (64x16) transposed
        {
            int r  = tid >> 2;               // 0..63
            int k4 = (tid & 3) << 2;
            float4 v = *reinterpret_cast<const float4*>(
                &g_cb[(size_t)(n0 + r) * DK + kc + k4]);
            Cs[k4 + 0][r] = v.x; Cs[k4 + 1][r] = v.y;
            Cs[k4 + 2][r] = v.z; Cs[k4 + 3][r] = v.w;
        }
        __syncthreads();
#pragma unroll
        for (int kk = 0; kk < 16; kk++) {
            float4 a0 = *reinterpret_cast<const float4*>(&Xs[kk][ty * 8]);
            float4 a1 = *reinterpret_cast<const float4*>(&Xs[kk][ty * 8 + 4]);
            float4 bv = *reinterpret_cast<const float4*>(&Cs[kk][tx * 4]);
            float a[8] = {a0.x, a0.y, a0.z, a0.w, a1.x, a1.y, a1.z, a1.w};
            float b[4] = {bv.x, bv.y, bv.z, bv.w};
#pragma unroll
            for (int i = 0; i < 8; i++)
#pragma unroll
                for (int j = 0; j < 4; j++)
                    acc[i][j] += a[i] * b[j];
        }
        __syncthreads();
    }

    // group of this code tile (tile never straddles a group boundary)
    const int bt = blockIdx.y;
    int grp, gstart;
    if (bt < 16)      { grp = 0; gstart = 0; }
    else if (bt < 24) { grp = 1; gstart = CB1_OFF; }
    else              { grp = 2; gstart = CB2_OFF; }

    float hn[4];
#pragma unroll
    for (int j = 0; j < 4; j++) hn[j] = g_halfnorm[n0 + tx * 4 + j];
    const int lbase = n0 - gstart + tx * 4;

#pragma unroll
    for (int i = 0; i < 8; i++) {
        unsigned long long best = ~0ULL;
#pragma unroll
        for (int j = 0; j < 4; j++) {
            float sc = hn[j] - acc[i][j];
            unsigned long long p =
                ((unsigned long long)f2ord(sc) << 32) | (unsigned int)(lbase + j);
            if (p < best) best = p;
        }
#pragma unroll
        for (int off = 8; off >= 1; off >>= 1) {
            unsigned long long q = __shfl_xor_sync(0xffffffffu, best, off);
            if (q < best) best = q;
        }
        if (tx == 0)
            atomicMin(&g_amin[(size_t)grp * NPTS + row0 + ty * 8 + i], best);
    }
}

// ---------------------------------------------------------------------------
// gather + outputs + loss partial sums + used flags. One block per row.
// ---------------------------------------------------------------------------
__global__ __launch_bounds__(128) void k_gather(const float* __restrict__ x,
                                                float* __restrict__ out) {
    const int row = blockIdx.x;
    const int tid = threadIdx.x;

    const int z  = (int)(g_amin[row] & 0xffffffffu);
    const int z1 = (int)(g_amin[NPTS + row] & 0xffffffffu);
    const int z2 = (int)(g_amin[2 * NPTS + row] & 0xffffffffu);
    if (tid == 0) g_used[z] = 1;

    const float4* xr = reinterpret_cast<const float4*>(&x[(size_t)row * DK]);
    const float4* m  = reinterpret_cast<const float4*>(&g_cb[(size_t)z * DK]);
    const float4* s1 = reinterpret_cast<const float4*>(&g_cb[(size_t)(CB1_OFF + z1) * DK]);
    const float4* s2 = reinterpret_cast<const float4*>(&g_cb[(size_t)(CB2_OFF + z2) * DK]);
    float4* om = reinterpret_cast<float4*>(&out[MAIN_OFF + (size_t)row * DK]);
    float4* os = reinterpret_cast<float4*>(&out[SUB_OFF + (size_t)row * DK]);

    float4 xv = xr[tid];
    float4 mv = m[tid];
    float4 a  = s1[tid];
    float4 b  = s2[tid];
    float4 sv = make_float4(0.5f * (a.x + b.x), 0.5f * (a.y + b.y),
                            0.5f * (a.z + b.z), 0.5f * (a.w + b.w));
    om[tid] = mv;
    os[tid] = sv;

    float dmx = mv.x - xv.x, dmy = mv.y - xv.y, dmz = mv.z - xv.z, dmw = mv.w - xv.w;
    float dsx = sv.x - xv.x, dsy = sv.y - xv.y, dsz = sv.z - xv.z, dsw = sv.w - xv.w;
    float lm = dmx * dmx + dmy * dmy + dmz * dmz + dmw * dmw;
    float ls = dsx * dsx + dsy * dsy + dsz * dsz + dsw * dsw;

#pragma unroll
    for (int off = 16; off >= 1; off >>= 1) {
        lm += __shfl_xor_sync(0xffffffffu, lm, off);
        ls += __shfl_xor_sync(0xffffffffu, ls, off);
    }
    __shared__ float sm[4], ss[4];
    int wid = tid >> 5, lane = tid & 31;
    if (lane == 0) { sm[wid] = lm; ss[wid] = ls; }
    __syncthreads();
    if (tid == 0) {
        float tlm = sm[0] + sm[1] + sm[2] + sm[3];
        float tls = ss[0] + ss[1] + ss[2] + ss[3];
        atomicAdd(&g_loss[0], tlm);
        atomicAdd(&g_loss[1], tls);
    }
}

// ---------------------------------------------------------------------------
// finalize: unique count + loss scalar
// ---------------------------------------------------------------------------
__global__ void k_final(const int* __restrict__ training, float* __restrict__ out) {
    const int tid = threadIdx.x;   // 256 threads
    int cnt = 0;
    for (int i = tid; i < NC0; i += 256) cnt += g_used[i];
#pragma unroll
    for (int off = 16; off >= 1; off >>= 1)
        cnt += __shfl_xor_sync(0xffffffffu, cnt, off);
    __shared__ int sc[8];
    int wid = tid >> 5, lane = tid & 31;
    if (lane == 0) sc[wid] = cnt;
    __syncthreads();
    if (tid == 0) {
        int total = 0;
#pragma unroll
        for (int w = 0; w < 8; w++) total += sc[w];
        float e_sum = g_loss[0] + g_loss[1];
        float loss = (*training != 0)
                   ? 1.25f * e_sum / ((float)NPTS * (float)DK)
                   : 0.0f;
        out[LOSS_OFF] = loss;
        out[UNIQ_OFF] = (float)total;
    }
}

// ---------------------------------------------------------------------------
extern "C" void kernel_launch(void* const* d_in, const int* in_sizes, int n_in,
                              void* d_out, int out_size) {
    const float* x  = (const float*)d_in[0];
    const float* c  = (const float*)d_in[1];
    const float* W1 = (const float*)d_in[2];
    const float* b1 = (const float*)d_in[3];
    const float* W2 = (const float*)d_in[4];
    const float* b2 = (const float*)d_in[5];
    const int* training = (const int*)d_in[6];
    float* out = (float*)d_out;

    k_init<<<(3 * NPTS + 255) / 256, 256>>>(out);
    k_copy_c<<<(NC0 * DK / 4 + 255) / 256, 256>>>(c);
    {
        dim3 g((NC1 + NC2) / 8, DK / 256);
        k_subc<<<g, 256>>>(c, W1, b1, W2, b2);
    }
    k_norm<<<(NCODES * 32 + 255) / 256, 256>>>();
    {
        dim3 g(NPTS / 128, NCODES / 64);   // 256 x 28
        k_score<<<g, 256>>>(x);
    }
    k_gather<<<NPTS, 128>>>(x, out);
    k_final<<<1, 256>>>(training, out);
}

// round 4
// speedup vs baseline: 1.7280x; 1.7280x over previous
#include <cuda_runtime.h>
#include <cuda_bf16.h>
#include <cstdint>

// Problem constants
#define NPTS   32768
#define DK     512
#define NC0    1024
#define NC1    512
#define NC2    256
#define NCODES 1792
#define CB1_OFF 1024
#define CB2_OFF 1536

// out layout: main_out | sub_out | loss | ms_k_i(16x512 zeros) | unique
#define MAIN_OFF 0
#define SUB_OFF  (NPTS*DK)
#define LOSS_OFF (2*NPTS*DK)
#define MS_OFF   (LOSS_OFF + 1)
#define MS_N     (16*DK)
#define UNIQ_OFF (MS_OFF + MS_N)

#define MARGIN 2.0f

// Scratch (device globals; no allocation allowed)
__device__ float              g_cb[NCODES * DK];
__device__ float              g_halfnorm[NCODES];
__device__ unsigned long long g_amin[3 * NPTS];     // packed approx (score,idx)
__device__ int                g_zres[3 * NPTS];     // final local indices
__device__ float              g_loss[2];
__device__ int                g_used[NC0];
__device__ __nv_bfloat16      g_xh[NPTS * DK];
__device__ __nv_bfloat16      g_ch[NCODES * DK];
__device__ float              g_sc[NPTS * NCODES];  // approx scores (225MB)

__device__ __forceinline__ unsigned int f2ord(float f) {
    unsigned int u = __float_as_uint(f);
    return (u & 0x80000000u) ? ~u : (u | 0x80000000u);
}
__device__ __forceinline__ float ord2f(unsigned int u) {
    unsigned int v = (u & 0x80000000u) ? (u & 0x7fffffffu) : ~u;
    return __uint_as_float(v);
}
__device__ __forceinline__ uint32_t smem_u32(const void* p) {
    uint32_t a;
    asm("{ .reg .u64 t; cvta.to.shared.u64 t, %1; cvt.u32.u64 %0, t; }" : "=r"(a) : "l"(p));
    return a;
}
__device__ __forceinline__ void cp16(uint32_t dst, const void* src) {
    asm volatile("cp.async.cg.shared.global [%0], [%1], 16;" :: "r"(dst), "l"(src));
}
#define CP_COMMIT() asm volatile("cp.async.commit_group;" ::: "memory")
#define CP_WAIT(n)  asm volatile("cp.async.wait_group %0;" :: "n"(n) : "memory")

__device__ __forceinline__ void ldsm4(uint32_t* r, uint32_t addr) {
    asm volatile("ldmatrix.sync.aligned.m8n8.x4.shared.b16 {%0,%1,%2,%3}, [%4];"
        : "=r"(r[0]), "=r"(r[1]), "=r"(r[2]), "=r"(r[3]) : "r"(addr));
}
__device__ __forceinline__ void mma_bf16(float* d, const uint32_t* a,
                                         uint32_t b0, uint32_t b1) {
    asm volatile("mma.sync.aligned.m16n8k16.row.col.f32.bf16.bf16.f32 "
        "{%0,%1,%2,%3}, {%4,%5,%6,%7}, {%8,%9}, {%0,%1,%2,%3};"
        : "+f"(d[0]), "+f"(d[1]), "+f"(d[2]), "+f"(d[3])
        : "r"(a[0]), "r"(a[1]), "r"(a[2]), "r"(a[3]), "r"(b0), "r"(b1));
}

// ---------------------------------------------------------------------------
__global__ void k_init(float* __restrict__ out) {
    int i = blockIdx.x * blockDim.x + threadIdx.x;
    if (i < 3 * NPTS) g_amin[i] = ~0ULL;
    if (i < MS_N)     out[MS_OFF + i] = 0.0f;
    if (i < NC0)      g_used[i] = 0;
    if (i < 2)        g_loss[i] = 0.0f;
}

__global__ void k_copy_c(const float* __restrict__ c) {
    int i = blockIdx.x * blockDim.x + threadIdx.x;
    if (i < NC0 * DK / 4)
        reinterpret_cast<float4*>(g_cb)[i] = reinterpret_cast<const float4*>(c)[i];
}

// sub codebooks (fp32 SIMT; bitwise identical to R1's passing version)
__global__ __launch_bounds__(256) void k_subc(
    const float* __restrict__ c,
    const float* __restrict__ W1, const float* __restrict__ b1,
    const float* __restrict__ W2, const float* __restrict__ b2)
{
    const int i0 = blockIdx.x * 8;
    const int d  = blockIdx.y * 256 + threadIdx.x;
    __shared__ float Ws[8][128];
    float acc[8];
#pragma unroll
    for (int r = 0; r < 8; r++) acc[r] = 0.0f;

    for (int j0 = 0; j0 < NC0; j0 += 128) {
#pragma unroll
        for (int l = 0; l < 4; l++) {
            int p = threadIdx.x + l * 256;
            int r = p >> 7, jj = p & 127;
            int gi = i0 + r;
            const float* Wrow = (gi < NC1) ? &W1[(size_t)gi * NC0]
                                           : &W2[(size_t)(gi - NC1) * NC0];
            Ws[r][jj] = Wrow[j0 + jj];
        }
        __syncthreads();
        for (int jj = 0; jj < 128; jj++) {
            float cv = c[(size_t)(j0 + jj) * DK + d];
#pragma unroll
            for (int r = 0; r < 8; r++) acc[r] += Ws[r][jj] * cv;
        }
        __syncthreads();
    }
#pragma unroll
    for (int r = 0; r < 8; r++) {
        int gi = i0 + r;
        float bias = (gi < NC1) ? b1[gi] : b2[gi - NC1];
        g_cb[(size_t)(CB1_OFF + gi) * DK + d] = acc[r] + bias;
    }
}

__global__ void k_norm() {
    int warp = (blockIdx.x * blockDim.x + threadIdx.x) >> 5;
    int lane = threadIdx.x & 31;
    if (warp >= NCODES) return;
    float s = 0.0f;
    for (int dd = lane; dd < DK; dd += 32) {
        float v = g_cb[(size_t)warp * DK + dd];
        s += v * v;
    }
#pragma unroll
    for (int off = 16; off >= 1; off >>= 1) s += __shfl_xor_sync(0xffffffffu, s, off);
    if (lane == 0) g_halfnorm[warp] = 0.5f * s;
}

// single-limb bf16 casts
__global__ void k_split_x(const float* __restrict__ x) {
    int i = blockIdx.x * blockDim.x + threadIdx.x;
    if (i >= NPTS * DK / 4) return;
    float4 v = reinterpret_cast<const float4*>(x)[i];
    __nv_bfloat162* ph = reinterpret_cast<__nv_bfloat162*>(g_xh);
    ph[2*i]   = {__float2bfloat16(v.x), __float2bfloat16(v.y)};
    ph[2*i+1] = {__float2bfloat16(v.z), __float2bfloat16(v.w)};
}
__global__ void k_split_c() {
    int i = blockIdx.x * blockDim.x + threadIdx.x;
    if (i >= NCODES * DK / 4) return;
    float4 v = reinterpret_cast<const float4*>(g_cb)[i];
    __nv_bfloat162* ph = reinterpret_cast<__nv_bfloat162*>(g_ch);
    ph[2*i]   = {__float2bfloat16(v.x), __float2bfloat16(v.y)};
    ph[2*i+1] = {__float2bfloat16(v.z), __float2bfloat16(v.w)};
}

// ---------------------------------------------------------------------------
// HMMA approx GEMM (hh term only, K=512) + approx argmin + full score store.
// CTA tile 128x128, 8 warps (4m x 2n), warp tile 32x64, BK=64, 3-stage cp.async.
// ---------------------------------------------------------------------------
__device__ __forceinline__ void stage_chunk(int chunk, int stage, uint32_t sbase,
                                            int tid, int row0, int c0) {
    const int koff = chunk << 6;
    const uint32_t sA = sbase + (uint32_t)stage * 32768u;
    const uint32_t sB = sA + 16384u;
#pragma unroll
    for (int p = 0; p < 4; p++) {
        int idx = tid + (p << 8);
        int row = idx >> 3, cc = idx & 7;
        uint32_t sw = (uint32_t)((cc ^ (row & 7)) << 4);
        cp16(sA + (uint32_t)row * 128u + sw,
             g_xh + (size_t)(row0 + row) * DK + koff + cc * 8);
        cp16(sB + (uint32_t)row * 128u + sw,
             g_ch + (size_t)(c0 + row) * DK + koff + cc * 8);
    }
    CP_COMMIT();
}

__global__ __launch_bounds__(256) void k_mma() {
    extern __shared__ __align__(16) char smem[];
    __shared__ float hn_s[128];
    const uint32_t sbase = smem_u32(smem);
    const int tid  = threadIdx.x;
    const int lane = tid & 31;
    const int warp = tid >> 5;
    const int wm = warp >> 1;
    const int wn = warp & 1;
    const int c0   = blockIdx.x << 7;     // 14 code tiles
    const int row0 = blockIdx.y << 7;     // 256 row tiles

    if (tid < 128) hn_s[tid] = g_halfnorm[c0 + tid];

    float acc[2][8][4];
#pragma unroll
    for (int i = 0; i < 2; i++)
#pragma unroll
        for (int j = 0; j < 8; j++)
#pragma unroll
            for (int k = 0; k < 4; k++) acc[i][j][k] = 0.0f;

    stage_chunk(0, 0, sbase, tid, row0, c0);
    stage_chunk(1, 1, sbase, tid, row0, c0);

    const int rsel = lane & 15;
    const int ksel = lane >> 4;

    for (int chunk = 0; chunk < 8; chunk++) {
        const int stage = chunk % 3;
        if (chunk < 6) CP_WAIT(1); else CP_WAIT(0);
        __syncthreads();
        if (chunk + 2 < 8)
            stage_chunk(chunk + 2, (chunk + 2) % 3, sbase, tid, row0, c0);

        const uint32_t sA = sbase + (uint32_t)stage * 32768u;
        const uint32_t sB = sA + 16384u;
#pragma unroll
        for (int q = 0; q < 4; q++) {
            uint32_t a[2][4], b[4][4];
            const int csel = (q << 1) + ksel;
#pragma unroll
            for (int mf = 0; mf < 2; mf++) {
                int row = (wm << 5) + (mf << 4) + rsel;
                ldsm4(a[mf], sA + (uint32_t)row * 128u
                           + (uint32_t)((csel ^ (row & 7)) << 4));
            }
#pragma unroll
            for (int bt = 0; bt < 4; bt++) {
                int row = (wn << 6) + (bt << 4) + rsel;
                ldsm4(b[bt], sB + (uint32_t)row * 128u
                           + (uint32_t)((csel ^ (row & 7)) << 4));
            }
#pragma unroll
            for (int mf = 0; mf < 2; mf++)
#pragma unroll
                for (int bt = 0; bt < 4; bt++) {
                    mma_bf16(acc[mf][bt * 2],     a[mf], b[bt][0], b[bt][2]);
                    mma_bf16(acc[mf][bt * 2 + 1], a[mf], b[bt][1], b[bt][3]);
                }
        }
        __syncthreads();
    }

    // epilogue: approx score = halfnorm - dot; store all scores + approx argmin
    const int grp = (blockIdx.x < 8) ? 0 : (blockIdx.x < 12) ? 1 : 2;
    const int g = lane >> 2, t = lane & 3;

#pragma unroll
    for (int mf = 0; mf < 2; mf++) {
#pragma unroll
        for (int rh = 0; rh < 2; rh++) {
            const int row = (wm << 5) + (mf << 4) + (rh << 3) + g;
            unsigned long long best = ~0ULL;
#pragma unroll
            for (int nf = 0; nf < 8; nf++) {
                int colb = (wn << 6) + (nf << 3) + (t << 1);
                float s0 = hn_s[colb]     - acc[mf][nf][rh * 2];
                float s1 = hn_s[colb + 1] - acc[mf][nf][rh * 2 + 1];
                *reinterpret_cast<float2*>(
                    &g_sc[(size_t)(row0 + row) * NCODES + c0 + colb]) = {s0, s1};
                unsigned long long p0 = ((unsigned long long)f2ord(s0) << 32) | (unsigned)colb;
                unsigned long long p1 = ((unsigned long long)f2ord(s1) << 32) | (unsigned)(colb + 1);
                if (p0 < best) best = p0;
                if (p1 < best) best = p1;
            }
#pragma unroll
            for (int off = 2; off >= 1; off >>= 1) {
                unsigned long long q2 = __shfl_xor_sync(0xffffffffu, best, off);
                if (q2 < best) best = q2;
            }
            if (t == 0)
                atomicMin(&g_amin[(size_t)grp * NPTS + row0 + row], best);
        }
    }
}

// ---------------------------------------------------------------------------
// exact rescore: one warp per (grp,row). Candidates = approx score within
// MARGIN of approx min; exact fp64 score from fp32 x / g_cb / halfnorm.
// ---------------------------------------------------------------------------
__global__ __launch_bounds__(256) void k_rescore(const float* __restrict__ x) {
    const int wid  = (blockIdx.x * blockDim.x + threadIdx.x) >> 5;
    const int lane = threadIdx.x & 31;
    const int grp = wid / NPTS;
    const int row = wid % NPTS;
    if (grp >= 3) return;

    const int gbase = (grp == 0) ? 0 : (grp == 1) ? CB1_OFF : CB2_OFF;
    const int gn    = (grp == 0) ? NC0 : (grp == 1) ? NC1 : NC2;

    const float thr = ord2f((unsigned)(g_amin[(size_t)grp * NPTS + row] >> 32)) + MARGIN;

    const float4* xr4 = reinterpret_cast<const float4*>(x + (size_t)row * DK);
    double bs = 1e300;
    int bi = 0;

    for (int it = 0; it < gn; it += 32) {
        float sa = g_sc[(size_t)row * NCODES + gbase + it + lane];
        unsigned mask = __ballot_sync(0xffffffffu, sa <= thr);
        while (mask) {
            int b = __ffs(mask) - 1;
            mask &= mask - 1;
            int li = it + b;
            const float4* cr4 = reinterpret_cast<const float4*>(
                g_cb + (size_t)(gbase + li) * DK);
            double ds = 0.0;
#pragma unroll
            for (int q = 0; q < 4; q++) {
                float4 xv = xr4[q * 32 + lane];
                float4 cv = cr4[q * 32 + lane];
                ds = fma((double)xv.x, (double)cv.x, ds);
                ds = fma((double)xv.y, (double)cv.y, ds);
                ds = fma((double)xv.z, (double)cv.z, ds);
                ds = fma((double)xv.w, (double)cv.w, ds);
            }
#pragma unroll
            for (int off = 16; off >= 1; off >>= 1)
                ds += __shfl_xor_sync(0xffffffffu, ds, off);
            double sc = (double)g_halfnorm[gbase + li] - ds;
            if (sc < bs) { bs = sc; bi = li; }   // ascending li -> first-min tie-break
        }
    }
    if (lane == 0) g_zres[(size_t)grp * NPTS + row] = bi;
}

// ---------------------------------------------------------------------------
__global__ __launch_bounds__(128) void k_gather(const float* __restrict__ x,
                                                float* __restrict__ out) {
    const int row = blockIdx.x;
    const int tid = threadIdx.x;

    const int z  = g_zres[row];
    const int z1 = g_zres[NPTS + row];
    const int z2 = g_zres[2 * NPTS + row];
    if (tid == 0) g_used[z] = 1;

    const float4* xr = reinterpret_cast<const float4*>(&x[(size_t)row * DK]);
    const float4* m  = reinterpret_cast<const float4*>(&g_cb[(size_t)z * DK]);
    const float4* s1 = reinterpret_cast<const float4*>(&g_cb[(size_t)(CB1_OFF + z1) * DK]);
    const float4* s2 = reinterpret_cast<const float4*>(&g_cb[(size_t)(CB2_OFF + z2) * DK]);
    float4* om = reinterpret_cast<float4*>(&out[MAIN_OFF + (size_t)row * DK]);
    float4* os = reinterpret_cast<float4*>(&out[SUB_OFF + (size_t)row * DK]);

    float4 xv = xr[tid];
    float4 mv = m[tid];
    float4 a  = s1[tid];
    float4 b  = s2[tid];
    float4 sv = make_float4(0.5f * (a.x + b.x), 0.5f * (a.y + b.y),
                            0.5f * (a.z + b.z), 0.5f * (a.w + b.w));
    om[tid] = mv;
    os[tid] = sv;

    float dmx = mv.x - xv.x, dmy = mv.y - xv.y, dmz = mv.z - xv.z, dmw = mv.w - xv.w;
    float dsx = sv.x - xv.x, dsy = sv.y - xv.y, dsz = sv.z - xv.z, dsw = sv.w - xv.w;
    float lm = dmx * dmx + dmy * dmy + dmz * dmz + dmw * dmw;
    float ls = dsx * dsx + dsy * dsy + dsz * dsz + dsw * dsw;

#pragma unroll
    for (int off = 16; off >= 1; off >>= 1) {
        lm += __shfl_xor_sync(0xffffffffu, lm, off);
        ls += __shfl_xor_sync(0xffffffffu, ls, off);
    }
    __shared__ float sm[4], ss[4];
    int wid = tid >> 5, lane = tid & 31;
    if (lane == 0) { sm[wid] = lm; ss[wid] = ls; }
    __syncthreads();
    if (tid == 0) {
        atomicAdd(&g_loss[0], sm[0] + sm[1] + sm[2] + sm[3]);
        atomicAdd(&g_loss[1], ss[0] + ss[1] + ss[2] + ss[3]);
    }
}

__global__ void k_final(const int* __restrict__ training, float* __restrict__ out) {
    const int tid = threadIdx.x;
    int cnt = 0;
    for (int i = tid; i < NC0; i += 256) cnt += g_used[i];
#pragma unroll
    for (int off = 16; off >= 1; off >>= 1) cnt += __shfl_xor_sync(0xffffffffu, cnt, off);
    __shared__ int sc[8];
    int wid = tid >> 5, lane = tid & 31;
    if (lane == 0) sc[wid] = cnt;
    __syncthreads();
    if (tid == 0) {
        int total = 0;
#pragma unroll
        for (int w = 0; w < 8; w++) total += sc[w];
        float e_sum = g_loss[0] + g_loss[1];
        out[LOSS_OFF] = (*training != 0)
                      ? 1.25f * e_sum / ((float)NPTS * (float)DK) : 0.0f;
        out[UNIQ_OFF] = (float)total;
    }
}

// ---------------------------------------------------------------------------
extern "C" void kernel_launch(void* const* d_in, const int* in_sizes, int n_in,
                              void* d_out, int out_size) {
    const float* x  = (const float*)d_in[0];
    const float* c  = (const float*)d_in[1];
    const float* W1 = (const float*)d_in[2];
    const float* b1 = (const float*)d_in[3];
    const float* W2 = (const float*)d_in[4];
    const float* b2 = (const float*)d_in[5];
    const int* training = (const int*)d_in[6];
    float* out = (float*)d_out;

    const int MMA_SMEM = 3 * 32768;   // 96KB
    cudaFuncSetAttribute(k_mma, cudaFuncAttributeMaxDynamicSharedMemorySize, MMA_SMEM);

    k_init<<<(3 * NPTS + 255) / 256, 256>>>(out);
    k_copy_c<<<(NC0 * DK / 4 + 255) / 256, 256>>>(c);
    {
        dim3 g((NC1 + NC2) / 8, DK / 256);
        k_subc<<<g, 256>>>(c, W1, b1, W2, b2);
    }
    k_split_x<<<(NPTS * DK / 4 + 255) / 256, 256>>>(x);
    k_split_c<<<(NCODES * DK / 4 + 255) / 256, 256>>>();
    k_norm<<<(NCODES * 32 + 255) / 256, 256>>>();
    {
        dim3 g(NCODES / 128, NPTS / 128);   // (14, 256)
        k_mma<<<g, 256, MMA_SMEM>>>();
    }
    k_rescore<<<(3 * NPTS * 32) / 256, 256>>>(x);
    k_gather<<<NPTS, 128>>>(x, out);
    k_final<<<1, 256>>>(training, out);
}

// round 5
// speedup vs baseline: 1.8323x; 1.0604x over previous
#include <cuda_runtime.h>
#include <cuda_bf16.h>
#include <cstdint>

// Problem constants
#define NPTS   32768
#define DK     512
#define NC0    1024
#define NC1    512
#define NC2    256
#define NCODES 1792
#define CB1_OFF 1024
#define CB2_OFF 1536

// out layout: main_out | sub_out | loss | ms_k_i(16x512 zeros) | unique
#define MAIN_OFF 0
#define SUB_OFF  (NPTS*DK)
#define LOSS_OFF (2*NPTS*DK)
#define MS_OFF   (LOSS_OFF + 1)
#define MS_N     (16*DK)
#define UNIQ_OFF (MS_OFF + MS_N)

#define MARGIN 2.0f

// Scratch (device globals; no allocation allowed)
__device__ float              g_cb[NCODES * DK];
__device__ float              g_halfnorm[NCODES];
__device__ unsigned long long g_amin[3 * NPTS];     // packed approx (score,idx)
__device__ float              g_loss[2];
__device__ int                g_used[NC0];
__device__ __nv_bfloat16      g_xh[NPTS * DK];
__device__ __nv_bfloat16      g_ch[NCODES * DK];
__device__ float              g_sc[NPTS * NCODES];  // approx scores (225MB)

__device__ __forceinline__ unsigned int f2ord(float f) {
    unsigned int u = __float_as_uint(f);
    return (u & 0x80000000u) ? ~u : (u | 0x80000000u);
}
__device__ __forceinline__ float ord2f(unsigned int u) {
    unsigned int v = (u & 0x80000000u) ? (u & 0x7fffffffu) : ~u;
    return __uint_as_float(v);
}
__device__ __forceinline__ uint32_t smem_u32(const void* p) {
    uint32_t a;
    asm("{ .reg .u64 t; cvta.to.shared.u64 t, %1; cvt.u32.u64 %0, t; }" : "=r"(a) : "l"(p));
    return a;
}
__device__ __forceinline__ void cp16(uint32_t dst, const void* src) {
    asm volatile("cp.async.cg.shared.global [%0], [%1], 16;" :: "r"(dst), "l"(src));
}
#define CP_COMMIT() asm volatile("cp.async.commit_group;" ::: "memory")
#define CP_WAIT(n)  asm volatile("cp.async.wait_group %0;" :: "n"(n) : "memory")

__device__ __forceinline__ void ldsm4(uint32_t* r, uint32_t addr) {
    asm volatile("ldmatrix.sync.aligned.m8n8.x4.shared.b16 {%0,%1,%2,%3}, [%4];"
        : "=r"(r[0]), "=r"(r[1]), "=r"(r[2]), "=r"(r[3]) : "r"(addr));
}
__device__ __forceinline__ void mma_bf16(float* d, const uint32_t* a,
                                         uint32_t b0, uint32_t b1) {
    asm volatile("mma.sync.aligned.m16n8k16.row.col.f32.bf16.bf16.f32 "
        "{%0,%1,%2,%3}, {%4,%5,%6,%7}, {%8,%9}, {%0,%1,%2,%3};"
        : "+f"(d[0]), "+f"(d[1]), "+f"(d[2]), "+f"(d[3])
        : "r"(a[0]), "r"(a[1]), "r"(a[2]), "r"(a[3]), "r"(b0), "r"(b1));
}

// ---------------------------------------------------------------------------
// prep1: init scratch + copy main codebook + split x to bf16  (launch #1)
// ---------------------------------------------------------------------------
__global__ __launch_bounds__(256) void k_prep1(const float* __restrict__ x,
                                               const float* __restrict__ c,
                                               float* __restrict__ out) {
    int i = blockIdx.x * blockDim.x + threadIdx.x;
    if (i < NPTS * DK / 4) {
        float4 v = reinterpret_cast<const float4*>(x)[i];
        __nv_bfloat162* ph = reinterpret_cast<__nv_bfloat162*>(g_xh);
        ph[2*i]   = {__float2bfloat16(v.x), __float2bfloat16(v.y)};
        ph[2*i+1] = {__float2bfloat16(v.z), __float2bfloat16(v.w)};
    }
    if (i < NC0 * DK / 4)
        reinterpret_cast<float4*>(g_cb)[i] = reinterpret_cast<const float4*>(c)[i];
    if (i < 3 * NPTS) g_amin[i] = ~0ULL;
    if (i < MS_N)     out[MS_OFF + i] = 0.0f;
    if (i < NC0)      g_used[i] = 0;
    if (i < 2)        g_loss[i] = 0.0f;
}

// ---------------------------------------------------------------------------
// sub codebooks (fp32 SIMT)                                      (launch #2)
// ---------------------------------------------------------------------------
__global__ __launch_bounds__(256) void k_subc(
    const float* __restrict__ c,
    const float* __restrict__ W1, const float* __restrict__ b1,
    const float* __restrict__ W2, const float* __restrict__ b2)
{
    const int i0 = blockIdx.x * 8;
    const int d  = blockIdx.y * 256 + threadIdx.x;
    __shared__ float Ws[8][128];
    float acc[8];
#pragma unroll
    for (int r = 0; r < 8; r++) acc[r] = 0.0f;

    for (int j0 = 0; j0 < NC0; j0 += 128) {
#pragma unroll
        for (int l = 0; l < 4; l++) {
            int p = threadIdx.x + l * 256;
            int r = p >> 7, jj = p & 127;
            int gi = i0 + r;
            const float* Wrow = (gi < NC1) ? &W1[(size_t)gi * NC0]
                                           : &W2[(size_t)(gi - NC1) * NC0];
            Ws[r][jj] = Wrow[j0 + jj];
        }
        __syncthreads();
        for (int jj = 0; jj < 128; jj++) {
            float cv = c[(size_t)(j0 + jj) * DK + d];
#pragma unroll
            for (int r = 0; r < 8; r++) acc[r] += Ws[r][jj] * cv;
        }
        __syncthreads();
    }
#pragma unroll
    for (int r = 0; r < 8; r++) {
        int gi = i0 + r;
        float bias = (gi < NC1) ? b1[gi] : b2[gi - NC1];
        g_cb[(size_t)(CB1_OFF + gi) * DK + d] = acc[r] + bias;
    }
}

// ---------------------------------------------------------------------------
// prep2: split all codebooks to bf16 + halfnorms (one warp/row)  (launch #3)
// ---------------------------------------------------------------------------
__global__ __launch_bounds__(256) void k_prep2() {
    const int warp = (blockIdx.x * blockDim.x + threadIdx.x) >> 5;
    const int lane = threadIdx.x & 31;
    if (warp >= NCODES) return;
    const float4* row4 = reinterpret_cast<const float4*>(g_cb + (size_t)warp * DK);
    __nv_bfloat162* ch2 = reinterpret_cast<__nv_bfloat162*>(g_ch + (size_t)warp * DK);
    float s = 0.0f;
#pragma unroll
    for (int q = 0; q < 4; q++) {
        float4 v = row4[q * 32 + lane];
        s += v.x * v.x + v.y * v.y + v.z * v.z + v.w * v.w;
        ch2[(q * 32 + lane) * 2]     = {__float2bfloat16(v.x), __float2bfloat16(v.y)};
        ch2[(q * 32 + lane) * 2 + 1] = {__float2bfloat16(v.z), __float2bfloat16(v.w)};
    }
#pragma unroll
    for (int off = 16; off >= 1; off >>= 1) s += __shfl_xor_sync(0xffffffffu, s, off);
    if (lane == 0) g_halfnorm[warp] = 0.5f * s;
}

// ---------------------------------------------------------------------------
// HMMA approx GEMM (hh only, K=512) + approx argmin + coalesced score store.
// CTA tile 128x128, 8 warps (4m x 2n), BK=64, 3-stage cp.async.   (launch #4)
// ---------------------------------------------------------------------------
__device__ __forceinline__ void stage_chunk(int chunk, int stage, uint32_t sbase,
                                            int tid, int row0, int c0) {
    const int koff = chunk << 6;
    const uint32_t sA = sbase + (uint32_t)stage * 32768u;
    const uint32_t sB = sA + 16384u;
#pragma unroll
    for (int p = 0; p < 4; p++) {
        int idx = tid + (p << 8);
        int row = idx >> 3, cc = idx & 7;
        uint32_t sw = (uint32_t)((cc ^ (row & 7)) << 4);
        cp16(sA + (uint32_t)row * 128u + sw,
             g_xh + (size_t)(row0 + row) * DK + koff + cc * 8);
        cp16(sB + (uint32_t)row * 128u + sw,
             g_ch + (size_t)(c0 + row) * DK + koff + cc * 8);
    }
    CP_COMMIT();
}

__global__ __launch_bounds__(256) void k_mma() {
    extern __shared__ __align__(16) char smem[];
    __shared__ float hn_s[128];
    const uint32_t sbase = smem_u32(smem);
    const int tid  = threadIdx.x;
    const int lane = tid & 31;
    const int warp = tid >> 5;
    const int wm = warp >> 1;
    const int wn = warp & 1;
    const int c0   = blockIdx.x << 7;     // 14 code tiles
    const int row0 = blockIdx.y << 7;     // 256 row tiles

    if (tid < 128) hn_s[tid] = g_halfnorm[c0 + tid];

    float acc[2][8][4];
#pragma unroll
    for (int i = 0; i < 2; i++)
#pragma unroll
        for (int j = 0; j < 8; j++)
#pragma unroll
            for (int k = 0; k < 4; k++) acc[i][j][k] = 0.0f;

    stage_chunk(0, 0, sbase, tid, row0, c0);
    stage_chunk(1, 1, sbase, tid, row0, c0);

    const int rsel = lane & 15;
    const int ksel = lane >> 4;

    for (int chunk = 0; chunk < 8; chunk++) {
        const int stage = chunk % 3;
        if (chunk < 6) CP_WAIT(1); else CP_WAIT(0);
        __syncthreads();
        if (chunk + 2 < 8)
            stage_chunk(chunk + 2, (chunk + 2) % 3, sbase, tid, row0, c0);

        const uint32_t sA = sbase + (uint32_t)stage * 32768u;
        const uint32_t sB = sA + 16384u;
#pragma unroll
        for (int q = 0; q < 4; q++) {
            uint32_t a[2][4], b[4][4];
            const int csel = (q << 1) + ksel;
#pragma unroll
            for (int mf = 0; mf < 2; mf++) {
                int row = (wm << 5) + (mf << 4) + rsel;
                ldsm4(a[mf], sA + (uint32_t)row * 128u
                           + (uint32_t)((csel ^ (row & 7)) << 4));
            }
#pragma unroll
            for (int bt = 0; bt < 4; bt++) {
                int row = (wn << 6) + (bt << 4) + rsel;
                ldsm4(b[bt], sB + (uint32_t)row * 128u
                           + (uint32_t)((csel ^ (row & 7)) << 4));
            }
#pragma unroll
            for (int mf = 0; mf < 2; mf++)
#pragma unroll
                for (int bt = 0; bt < 4; bt++) {
                    mma_bf16(acc[mf][bt * 2],     a[mf], b[bt][0], b[bt][2]);
                    mma_bf16(acc[mf][bt * 2 + 1], a[mf], b[bt][1], b[bt][3]);
                }
        }
        __syncthreads();
    }

    // epilogue: approx score -> smem stage (coalesced store) + register argmin
    const int grp = (blockIdx.x < 8) ? 0 : (blockIdx.x < 12) ? 1 : 2;
    const int g = lane >> 2, t = lane & 3;
    float* scs = reinterpret_cast<float*>(smem);   // [128][132] padded

#pragma unroll
    for (int mf = 0; mf < 2; mf++) {
#pragma unroll
        for (int rh = 0; rh < 2; rh++) {
            const int row = (wm << 5) + (mf << 4) + (rh << 3) + g;
            unsigned long long best = ~0ULL;
#pragma unroll
            for (int nf = 0; nf < 8; nf++) {
                int colb = (wn << 6) + (nf << 3) + (t << 1);
                float s0 = hn_s[colb]     - acc[mf][nf][rh * 2];
                float s1 = hn_s[colb + 1] - acc[mf][nf][rh * 2 + 1];
                scs[row * 132 + colb]     = s0;
                scs[row * 132 + colb + 1] = s1;
                unsigned long long p0 = ((unsigned long long)f2ord(s0) << 32) | (unsigned)colb;
                unsigned long long p1 = ((unsigned long long)f2ord(s1) << 32) | (unsigned)(colb + 1);
                if (p0 < best) best = p0;
                if (p1 < best) best = p1;
            }
#pragma unroll
            for (int off = 2; off >= 1; off >>= 1) {
                unsigned long long q2 = __shfl_xor_sync(0xffffffffu, best, off);
                if (q2 < best) best = q2;
            }
            if (t == 0)
                atomicMin(&g_amin[(size_t)grp * NPTS + row0 + row], best);
        }
    }
    __syncthreads();

    // coalesced copy smem -> g_sc (128B segments)
#pragma unroll
    for (int r8 = 0; r8 < 128; r8 += 8) {
        int row = r8 + (tid >> 5);
        int c4  = (tid & 31) << 2;
        float4 v = *reinterpret_cast<const float4*>(&scs[row * 132 + c4]);
        *reinterpret_cast<float4*>(
            &g_sc[(size_t)(row0 + row) * NCODES + c0 + c4]) = v;
    }
}

// ---------------------------------------------------------------------------
// fused exact-rescore + gather: one block (128 thr) per row.     (launch #5)
// warps 0-2: candidate rescore for grp 0-2 (fp64-exact); then gather+loss.
// ---------------------------------------------------------------------------
__global__ __launch_bounds__(128) void k_rg(const float* __restrict__ x,
                                            float* __restrict__ out) {
    const int row = blockIdx.x;
    const int tid = threadIdx.x;
    const int lane = tid & 31;
    const int w = tid >> 5;

    __shared__ float xs[DK];
    __shared__ int zres_s[3];

    reinterpret_cast<float4*>(xs)[tid] =
        reinterpret_cast<const float4*>(x + (size_t)row * DK)[tid];
    __syncthreads();

    if (w < 3) {
        const int gbase = (w == 0) ? 0 : (w == 1) ? CB1_OFF : CB2_OFF;
        const int gn    = (w == 0) ? NC0 : (w == 1) ? NC1 : NC2;
        const float thr =
            ord2f((unsigned)(g_amin[(size_t)w * NPTS + row] >> 32)) + MARGIN;
        const float4* xs4 = reinterpret_cast<const float4*>(xs);
        double bs = 1e300;
        int bi = 0;
        for (int it = 0; it < gn; it += 32) {
            float sa = g_sc[(size_t)row * NCODES + gbase + it + lane];
            unsigned mask = __ballot_sync(0xffffffffu, sa <= thr);
            while (mask) {
                int b = __ffs(mask) - 1;
                mask &= mask - 1;
                int li = it + b;
                const float4* cr4 = reinterpret_cast<const float4*>(
                    g_cb + (size_t)(gbase + li) * DK);
                double ds = 0.0;
#pragma unroll
                for (int q = 0; q < 4; q++) {
                    float4 xv = xs4[q * 32 + lane];
                    float4 cv = cr4[q * 32 + lane];
                    ds = fma((double)xv.x, (double)cv.x, ds);
                    ds = fma((double)xv.y, (double)cv.y, ds);
                    ds = fma((double)xv.z, (double)cv.z, ds);
                    ds = fma((double)xv.w, (double)cv.w, ds);
                }
#pragma unroll
                for (int off = 16; off >= 1; off >>= 1)
                    ds += __shfl_xor_sync(0xffffffffu, ds, off);
                double sc = (double)g_halfnorm[gbase + li] - ds;
                if (sc < bs) { bs = sc; bi = li; }
            }
        }
        if (lane == 0) zres_s[w] = bi;
    }
    __syncthreads();

    const int z  = zres_s[0];
    const int z1 = zres_s[1];
    const int z2 = zres_s[2];
    if (tid == 0) g_used[z] = 1;

    const float4* m  = reinterpret_cast<const float4*>(&g_cb[(size_t)z * DK]);
    const float4* s1 = reinterpret_cast<const float4*>(&g_cb[(size_t)(CB1_OFF + z1) * DK]);
    const float4* s2 = reinterpret_cast<const float4*>(&g_cb[(size_t)(CB2_OFF + z2) * DK]);
    float4* om = reinterpret_cast<float4*>(&out[MAIN_OFF + (size_t)row * DK]);
    float4* os = reinterpret_cast<float4*>(&out[SUB_OFF + (size_t)row * DK]);

    float4 xv = reinterpret_cast<const float4*>(xs)[tid];
    float4 mv = m[tid];
    float4 a  = s1[tid];
    float4 b  = s2[tid];
    float4 sv = make_float4(0.5f * (a.x + b.x), 0.5f * (a.y + b.y),
                            0.5f * (a.z + b.z), 0.5f * (a.w + b.w));
    om[tid] = mv;
    os[tid] = sv;

    float dmx = mv.x - xv.x, dmy = mv.y - xv.y, dmz = mv.z - xv.z, dmw = mv.w - xv.w;
    float dsx = sv.x - xv.x, dsy = sv.y - xv.y, dsz = sv.z - xv.z, dsw = sv.w - xv.w;
    float lm = dmx * dmx + dmy * dmy + dmz * dmz + dmw * dmw;
    float ls = dsx * dsx + dsy * dsy + dsz * dsz + dsw * dsw;

#pragma unroll
    for (int off = 16; off >= 1; off >>= 1) {
        lm += __shfl_xor_sync(0xffffffffu, lm, off);
        ls += __shfl_xor_sync(0xffffffffu, ls, off);
    }
    __shared__ float sm[4], ss[4];
    if (lane == 0) { sm[w] = lm; ss[w] = ls; }
    __syncthreads();
    if (tid == 0) {
        atomicAdd(&g_loss[0], sm[0] + sm[1] + sm[2] + sm[3]);
        atomicAdd(&g_loss[1], ss[0] + ss[1] + ss[2] + ss[3]);
    }
}

// ---------------------------------------------------------------------------
__global__ void k_final(const int* __restrict__ training, float* __restrict__ out) {
    const int tid = threadIdx.x;
    int cnt = 0;
    for (int i = tid; i < NC0; i += 256) cnt += g_used[i];
#pragma unroll
    for (int off = 16; off >= 1; off >>= 1) cnt += __shfl_xor_sync(0xffffffffu, cnt, off);
    __shared__ int sc[8];
    int wid = tid >> 5, lane = tid & 31;
    if (lane == 0) sc[wid] = cnt;
    __syncthreads();
    if (tid == 0) {
        int total = 0;
#pragma unroll
        for (int w = 0; w < 8; w++) total += sc[w];
        float e_sum = g_loss[0] + g_loss[1];
        out[LOSS_OFF] = (*training != 0)
                      ? 1.25f * e_sum / ((float)NPTS * (float)DK) : 0.0f;
        out[UNIQ_OFF] = (float)total;
    }
}

// ---------------------------------------------------------------------------
extern "C" void kernel_launch(void* const* d_in, const int* in_sizes, int n_in,
                              void* d_out, int out_size) {
    const float* x  = (const float*)d_in[0];
    const float* c  = (const float*)d_in[1];
    const float* W1 = (const float*)d_in[2];
    const float* b1 = (const float*)d_in[3];
    const float* W2 = (const float*)d_in[4];
    const float* b2 = (const float*)d_in[5];
    const int* training = (const int*)d_in[6];
    float* out = (float*)d_out;

    const int MMA_SMEM = 128 * 132 * 4;   // 67584 >= 3*32768 staging? no: use max
    const int MMA_SMEM_FULL = (3 * 32768 > MMA_SMEM) ? 3 * 32768 : MMA_SMEM;
    cudaFuncSetAttribute(k_mma, cudaFuncAttributeMaxDynamicSharedMemorySize,
                         MMA_SMEM_FULL);

    k_prep1<<<(NPTS * DK / 4 + 255) / 256, 256>>>(x, c, out);       // #1
    {
        dim3 g((NC1 + NC2) / 8, DK / 256);
        k_subc<<<g, 256>>>(c, W1, b1, W2, b2);                       // #2
    }
    k_prep2<<<(NCODES * 32 + 255) / 256, 256>>>();                   // #3
    {
        dim3 g(NCODES / 128, NPTS / 128);   // (14, 256)
        k_mma<<<g, 256, MMA_SMEM_FULL>>>();                          // #4
    }
    k_rg<<<NPTS, 128>>>(x, out);                                     // #5
    k_final<<<1, 256>>>(training, out);                              // #6
}